// round 6
// baseline (speedup 1.0000x reference)
#include <cuda_runtime.h>

#define HW   9216            // 96*96
#define NPIX 589824          // 64*HW

#define INV_LOG49 0.2569487252483261f
#define INV_LOG81 0.2275598569527368f
#define L2E       1.4426950408889634f

__device__ __forceinline__ float ex2(float x) {
    float y;
    asm("ex2.approx.ftz.f32 %0, %1;" : "=f"(y) : "f"(x));
    return y;
}

// Load slice [START, START+CNT) into registers + partial argmax (first-occurrence).
template<int START, int CNT>
__device__ __forceinline__ void load_argmax(const float* __restrict__ px,
                                            float* val, float& pm, int& pi) {
#pragma unroll
    for (int k = 0; k < CNT; k++)
        val[k] = px[(size_t)(START + k) * HW];
    pm = val[0];
    pi = START;
#pragma unroll
    for (int k = 1; k < CNT; k++)
        if (val[k] > pm) { pm = val[k]; pi = START + k; }
}

template<int START, int CNT>
__device__ __forceinline__ void moments(const float* val, float nML2E,
                                        unsigned rowbits, unsigned colbits,
                                        float* acc) {
#pragma unroll
    for (int k = 0; k < CNT; k++) {
        const int i = START + k;        // compile-time
        const int u = i / 9;
        const int v = i - u * 9;
        // row term CSE'd per u-row by the compiler
        const unsigned cm = ((rowbits >> u) & 1u) ? colbits : 0u;
        float e = ex2(fmaf(val[k], L2E, nML2E));     // exp(val - M)
        acc[0] += e;                                  // Sg
        acc[1]  = fmaf(val[k], e, acc[1]);            // T'g = sum val*e
        if ((cm >> v) & 1u) {
            acc[2] += e;                              // Sl
            acc[3]  = fmaf(val[k], e, acc[3]);        // T'l
            acc[4]  = fmaf(e, (float)(u - 4), acc[4]); // Sfx (imm FFMA)
            acc[5]  = fmaf(e, (float)(v - 4), acc[5]); // Sfy (imm FFMA)
        }
    }
}

// Slice starts/counts: {0:11, 11:10, 21:10, 31:10, 41:10, 51:10, 61:10, 71:10}
__global__ __launch_bounds__(256, 7)
void vcn_kernel(const float* __restrict__ x, float* __restrict__ out) {
    const int lane = threadIdx.x;      // 0..31 : pixel within CTA group
    const int yy   = threadIdx.y;      // 0..7  : plane slice

    const int pixel = blockIdx.x * 32 + lane;
    const int b  = pixel / HW;
    const int hw = pixel - b * HW;
    const float* px = x + (size_t)b * 81 * HW + hw;

    __shared__ float smax[8][32];
    __shared__ int   sidx[8][32];
    __shared__ float spart[6][8][32];

    float val[11];
    float pm;
    int   pi;

    switch (yy) {
        case 0:  load_argmax< 0, 11>(px, val, pm, pi); break;
        case 1:  load_argmax<11, 10>(px, val, pm, pi); break;
        case 2:  load_argmax<21, 10>(px, val, pm, pi); break;
        case 3:  load_argmax<31, 10>(px, val, pm, pi); break;
        case 4:  load_argmax<41, 10>(px, val, pm, pi); break;
        case 5:  load_argmax<51, 10>(px, val, pm, pi); break;
        case 6:  load_argmax<61, 10>(px, val, pm, pi); break;
        default: load_argmax<71, 10>(px, val, pm, pi); break;
    }
    smax[yy][lane] = pm;
    sidx[yy][lane] = pi;
    __syncthreads();

    // Combine argmax: ascending slice order + strict '>' keeps first occurrence.
    float M    = smax[0][lane];
    int   amax = sidx[0][lane];
#pragma unroll
    for (int q = 1; q < 8; q++) {
        float m2 = smax[q][lane];
        if (m2 > M) { M = m2; amax = sidx[q][lane]; }
    }

    const int iu = amax / 9;
    const int iv = amax - iu * 9;
    const unsigned rowbits = (0x7Fu << iu) >> 3;   // bit u set iff |u-iu|<=3
    const unsigned colbits = (0x7Fu << iv) >> 3;

    float acc[6] = {0.f, 0.f, 0.f, 0.f, 0.f, 0.f};
    const float nML2E = -M * L2E;
    switch (yy) {
        case 0:  moments< 0, 11>(val, nML2E, rowbits, colbits, acc); break;
        case 1:  moments<11, 10>(val, nML2E, rowbits, colbits, acc); break;
        case 2:  moments<21, 10>(val, nML2E, rowbits, colbits, acc); break;
        case 3:  moments<31, 10>(val, nML2E, rowbits, colbits, acc); break;
        case 4:  moments<41, 10>(val, nML2E, rowbits, colbits, acc); break;
        case 5:  moments<51, 10>(val, nML2E, rowbits, colbits, acc); break;
        case 6:  moments<61, 10>(val, nML2E, rowbits, colbits, acc); break;
        default: moments<71, 10>(val, nML2E, rowbits, colbits, acc); break;
    }
#pragma unroll
    for (int j = 0; j < 6; j++) spart[j][yy][lane] = acc[j];
    __syncthreads();

    // Parallel epilogue: warp yy produces output channel yy (yy<4).
    // ch0: outx = Sfx/Sl      needs acc4, acc2
    // ch1: outy = Sfy/Sl      needs acc5, acc2
    // ch2: entl               needs acc3, acc2
    // ch3: entg               needs acc1, acc0
    if (yy < 4) {
        const int jn = (yy == 3) ? 1 : (yy == 0 ? 4 : (yy == 1 ? 5 : 3)); // numerator acc
        const int jd = (yy == 3) ? 0 : 2;                                  // denominator acc
        float num = 0.f, den = 0.f;
#pragma unroll
        for (int q = 0; q < 8; q++) {
            num += spart[jn][q][lane];
            den += spart[jd][q][lane];
        }
        float invden = 1.0f / den;
        float r;
        if (yy < 2) {
            r = num * invden;                                   // flow
        } else if (yy == 2) {
            r = (__logf(den) - num * invden + M) * INV_LOG49;   // local entropy
        } else {
            r = (__logf(den) - num * invden + M) * INV_LOG81;   // global entropy
        }
        out[(size_t)b * 4 * HW + (size_t)yy * HW + hw] = r;
    }
}

extern "C" void kernel_launch(void* const* d_in, const int* in_sizes, int n_in,
                              void* d_out, int out_size) {
    const float* x = (const float*)d_in[0];
    float* out = (float*)d_out;
    dim3 block(32, 8);
    vcn_kernel<<<NPIX / 32, block>>>(x, out);   // 18432 blocks, 256 threads
}

// round 7
// speedup vs baseline: 1.1349x; 1.1349x over previous
#include <cuda_runtime.h>

#define HW   9216            // 96*96
#define NPIX 589824          // 64*HW

#define INV_LOG49 0.2569487252483261f
#define INV_LOG81 0.2275598569527368f
#define L2E       1.4426950408889634f

__device__ __forceinline__ float ex2(float x) {
    float y;
    asm("ex2.approx.ftz.f32 %0, %1;" : "=f"(y) : "f"(x));
    return y;
}

// Load slice [START, START+CNT) into registers + partial argmax (first-occurrence).
template<int START, int CNT>
__device__ __forceinline__ void load_argmax(const float* __restrict__ px,
                                            float* val, float& pm, int& pi) {
#pragma unroll
    for (int k = 0; k < CNT; k++)
        val[k] = px[(size_t)(START + k) * HW];
    pm = val[0];
    pi = START;
#pragma unroll
    for (int k = 1; k < CNT; k++)
        if (val[k] > pm) { pm = val[k]; pi = START + k; }
}

// Row-factored moments: per element all-fma-pipe; row mask applied per fragment.
template<int START, int CNT>
__device__ __forceinline__ void moments(const float* val, float nML2E,
                                        unsigned rowbits, const float* mcolf,
                                        float* acc) {
    float rS = 0.f, rT = 0.f, rFy = 0.f;   // row-fragment partials (col-masked)
#pragma unroll
    for (int k = 0; k < CNT; k++) {
        const int i = START + k;           // compile-time
        const int u = i / 9;
        const int v = i - u * 9;
        float e = ex2(fmaf(val[k], L2E, nML2E));   // exp(val - M)
        acc[0] += e;                                // Sg
        acc[1]  = fmaf(val[k], e, acc[1]);          // T'g = sum val*e
        float mev = e * mcolf[v];                   // col-masked e (0 or e)
        rS += mev;
        rT  = fmaf(val[k], mev, rT);
        rFy = fmaf(mev, (float)(v - 4), rFy);       // FFMA-imm
        if (v == 8 || k == CNT - 1) {               // fragment end (compile-time)
            float mr = ((rowbits >> u) & 1u) ? 1.0f : 0.0f;
            float t  = rS * mr;
            acc[2] += t;                            // Sl
            acc[3]  = fmaf(rT,  mr, acc[3]);        // T'l
            acc[4]  = fmaf(t,   (float)(u - 4), acc[4]); // Sfx
            acc[5]  = fmaf(rFy, mr, acc[5]);        // Sfy
            rS = 0.f; rT = 0.f; rFy = 0.f;
        }
    }
}

__global__ __launch_bounds__(128)
void vcn_kernel(const float* __restrict__ x, float* __restrict__ out) {
    const int lane = threadIdx.x;
    const int yy   = threadIdx.y;

    const int pixel = blockIdx.x * 32 + lane;
    const int b  = pixel / HW;
    const int hw = pixel - b * HW;
    const float* px = x + (size_t)b * 81 * HW + hw;

    __shared__ float smax[4][32];
    __shared__ int   sidx[4][32];
    __shared__ float spart[6][4][32];

    float val[21];
    float pm;
    int   pi;

    switch (yy) {
        case 0:  load_argmax< 0, 21>(px, val, pm, pi); break;
        case 1:  load_argmax<21, 20>(px, val, pm, pi); break;
        case 2:  load_argmax<41, 20>(px, val, pm, pi); break;
        default: load_argmax<61, 20>(px, val, pm, pi); break;
    }
    smax[yy][lane] = pm;
    sidx[yy][lane] = pi;
    __syncthreads();

    // Combine argmax (ascending yy + strict '>' keeps first occurrence).
    float M    = smax[0][lane];
    int   amax = sidx[0][lane];
#pragma unroll
    for (int q = 1; q < 4; q++) {
        float m2 = smax[q][lane];
        if (m2 > M) { M = m2; amax = sidx[q][lane]; }
    }

    const int iu = amax / 9;
    const int iv = amax - iu * 9;
    const unsigned rowbits = (0x7Fu << iu) >> 3;   // bit u set iff |u-iu|<=3
    const unsigned colbits = (0x7Fu << iv) >> 3;

    // Column mask as floats (one-time; empties the alu pipe in the hot loop).
    float mcolf[9];
#pragma unroll
    for (int v = 0; v < 9; v++)
        mcolf[v] = ((colbits >> v) & 1u) ? 1.0f : 0.0f;

    float acc[6] = {0.f, 0.f, 0.f, 0.f, 0.f, 0.f};
    const float nML2E = -M * L2E;
    switch (yy) {
        case 0:  moments< 0, 21>(val, nML2E, rowbits, mcolf, acc); break;
        case 1:  moments<21, 20>(val, nML2E, rowbits, mcolf, acc); break;
        case 2:  moments<41, 20>(val, nML2E, rowbits, mcolf, acc); break;
        default: moments<61, 20>(val, nML2E, rowbits, mcolf, acc); break;
    }
#pragma unroll
    for (int j = 0; j < 6; j++) spart[j][yy][lane] = acc[j];
    __syncthreads();

    // Final combine + output (warp-row 0; coalesced stores).
    if (yy == 0) {
#pragma unroll
        for (int q = 1; q < 4; q++)
#pragma unroll
            for (int j = 0; j < 6; j++) acc[j] += spart[j][q][lane];

        float Sg = acc[0], Tg = acc[1], Sl = acc[2], Tl = acc[3];
        float invSl = 1.0f / Sl;
        float invSg = 1.0f / Sg;
        // -sum p log p = log S - sum(val*e)/S + M
        float entl = (__logf(Sl) - Tl * invSl + M) * INV_LOG49;
        float entg = (__logf(Sg) - Tg * invSg + M) * INV_LOG81;

        float* o = out + (size_t)b * 4 * HW + hw;
        o[0]      = acc[4] * invSl;
        o[HW]     = acc[5] * invSl;
        o[2 * HW] = entl;
        o[3 * HW] = entg;
    }
}

extern "C" void kernel_launch(void* const* d_in, const int* in_sizes, int n_in,
                              void* d_out, int out_size) {
    const float* x = (const float*)d_in[0];
    float* out = (float*)d_out;
    dim3 block(32, 4);
    vcn_kernel<<<NPIX / 32, block>>>(x, out);   // 18432 blocks
}